// round 1
// baseline (speedup 1.0000x reference)
#include <cuda_runtime.h>
#include <math.h>

#define NTOK 3072
#define DIM  768
#define NHEAD 12
#define HDIM 64

// ---------------- static device scratch (no allocations allowed) ----------------
__device__ float g_qa[NTOK * DIM];
__device__ float g_ka[NTOK * DIM];
__device__ float g_Q [NTOK * DIM];
__device__ float g_K [NTOK * DIM];
__device__ float g_V [NTOK * DIM];
__device__ float g_O [NTOK * DIM];
__device__ float g_S [(size_t)NTOK * NTOK];   // logits / scores / attn (reused)
__device__ float g_Wa[(size_t)NTOK * NTOK];   // head-averaged attention weights
__device__ float g_Wf[(size_t)NTOK * NTOK];   // fused structural*attention weights
__device__ double g_stats[2];                 // sum, sumsq of Wf

// ---------------- warp reduce helpers ----------------
__device__ __forceinline__ float warp_max(float v) {
    #pragma unroll
    for (int o = 16; o; o >>= 1) v = fmaxf(v, __shfl_xor_sync(0xffffffffu, v, o));
    return v;
}
__device__ __forceinline__ float warp_sum(float v) {
    #pragma unroll
    for (int o = 16; o; o >>= 1) v += __shfl_xor_sync(0xffffffffu, v, o);
    return v;
}

// ---------------- GEMM: C[i,j] = scale * sum_k A[i,k]*B[j,k] (+bias[j]) ----------------
// NT layout: both A and B row-major, dot of A-row with B-row. Tiles 128x128x16, 8x8/thread.
// Requires M%128==0, Ncols%128==0, K%16==0 (all shapes here satisfy this).
__global__ __launch_bounds__(256) void gemm_nt(
    const float* __restrict__ A, int lda,
    const float* __restrict__ B, int ldb,
    float* __restrict__ C, int ldc,
    int K, const float* __restrict__ bias, float scale)
{
    constexpr int BM = 128, BN = 128, BK = 16, TM = 8, TN = 8;
    __shared__ float As[BK][BM + 4];
    __shared__ float Bs[BK][BN + 4];

    const int tid = threadIdx.x;
    const int row0 = blockIdx.y * BM;
    const int col0 = blockIdx.x * BN;
    const int ty = tid / (BN / TN);   // 0..15
    const int tx = tid % (BN / TN);   // 0..15

    float acc[TM][TN];
    #pragma unroll
    for (int i = 0; i < TM; i++)
        #pragma unroll
        for (int j = 0; j < TN; j++) acc[i][j] = 0.f;

    for (int k0 = 0; k0 < K; k0 += BK) {
        #pragma unroll
        for (int t = 0; t < (BM * BK) / 256; ++t) {
            int idx = tid + t * 256;
            int r = idx >> 4, kk = idx & 15;
            As[kk][r] = A[(size_t)(row0 + r) * lda + k0 + kk];
        }
        #pragma unroll
        for (int t = 0; t < (BN * BK) / 256; ++t) {
            int idx = tid + t * 256;
            int r = idx >> 4, kk = idx & 15;
            Bs[kk][r] = B[(size_t)(col0 + r) * ldb + k0 + kk];
        }
        __syncthreads();
        #pragma unroll
        for (int kk = 0; kk < BK; ++kk) {
            float ar[TM], br[TN];
            #pragma unroll
            for (int i = 0; i < TM; i++) ar[i] = As[kk][ty * TM + i];
            #pragma unroll
            for (int j = 0; j < TN; j++) br[j] = Bs[kk][tx * TN + j];
            #pragma unroll
            for (int i = 0; i < TM; i++)
                #pragma unroll
                for (int j = 0; j < TN; j++)
                    acc[i][j] += ar[i] * br[j];
        }
        __syncthreads();
    }

    #pragma unroll
    for (int i = 0; i < TM; i++) {
        int r = row0 + ty * TM + i;
        #pragma unroll
        for (int j = 0; j < TN; j++) {
            int c = col0 + tx * TN + j;
            float v = acc[i][j] * scale;
            if (bias) v += bias[c];
            C[(size_t)r * ldc + c] = v;
        }
    }
}

// ---------------- GEMM: C = A @ B (+bias), A row-major MxK, B row-major KxN ----------------
__global__ __launch_bounds__(256) void gemm_nn(
    const float* __restrict__ A, int lda,
    const float* __restrict__ B, int ldb,
    float* __restrict__ C, int ldc,
    int K, const float* __restrict__ bias, float scale)
{
    constexpr int BM = 128, BN = 128, BK = 16, TM = 8, TN = 8;
    __shared__ float As[BK][BM + 4];
    __shared__ float Bs[BK][BN + 4];

    const int tid = threadIdx.x;
    const int row0 = blockIdx.y * BM;
    const int col0 = blockIdx.x * BN;
    const int ty = tid / (BN / TN);
    const int tx = tid % (BN / TN);

    float acc[TM][TN];
    #pragma unroll
    for (int i = 0; i < TM; i++)
        #pragma unroll
        for (int j = 0; j < TN; j++) acc[i][j] = 0.f;

    for (int k0 = 0; k0 < K; k0 += BK) {
        #pragma unroll
        for (int t = 0; t < (BM * BK) / 256; ++t) {
            int idx = tid + t * 256;
            int r = idx >> 4, kk = idx & 15;
            As[kk][r] = A[(size_t)(row0 + r) * lda + k0 + kk];
        }
        #pragma unroll
        for (int t = 0; t < (BN * BK) / 256; ++t) {
            int idx = tid + t * 256;
            int c = idx & 127, kk = idx >> 7;
            Bs[kk][c] = B[(size_t)(k0 + kk) * ldb + col0 + c];
        }
        __syncthreads();
        #pragma unroll
        for (int kk = 0; kk < BK; ++kk) {
            float ar[TM], br[TN];
            #pragma unroll
            for (int i = 0; i < TM; i++) ar[i] = As[kk][ty * TM + i];
            #pragma unroll
            for (int j = 0; j < TN; j++) br[j] = Bs[kk][tx * TN + j];
            #pragma unroll
            for (int i = 0; i < TM; i++)
                #pragma unroll
                for (int j = 0; j < TN; j++)
                    acc[i][j] += ar[i] * br[j];
        }
        __syncthreads();
    }

    #pragma unroll
    for (int i = 0; i < TM; i++) {
        int r = row0 + ty * TM + i;
        #pragma unroll
        for (int j = 0; j < TN; j++) {
            int c = col0 + tx * TN + j;
            float v = acc[i][j] * scale;
            if (bias) v += bias[c];
            C[(size_t)r * ldc + c] = v;
        }
    }
}

// ---------------- per-head row softmax of g_S, accumulate average into g_Wa ----------------
__global__ __launch_bounds__(256) void softmax_acc_kernel(int first)
{
    __shared__ float z[NTOK];
    __shared__ float redA[8];
    __shared__ float redB[8];
    const int i = blockIdx.x, tid = threadIdx.x;
    const int lane = tid & 31, wid = tid >> 5;
    const float* row = g_S + (size_t)i * NTOK;

    float lmax = -1e30f;
    for (int j = tid; j < NTOK; j += 256) {
        float v = row[j];
        z[j] = v;
        lmax = fmaxf(lmax, v);
    }
    lmax = warp_max(lmax);
    if (lane == 0) redA[wid] = lmax;
    __syncthreads();
    if (wid == 0) {
        float t = (lane < 8) ? redA[lane] : -1e30f;
        t = warp_max(t);
        if (lane == 0) redA[0] = t;
    }
    __syncthreads();
    const float m = redA[0];

    float lsum = 0.f;
    for (int j = tid; j < NTOK; j += 256) lsum += expf(z[j] - m);
    lsum = warp_sum(lsum);
    if (lane == 0) redB[wid] = lsum;
    __syncthreads();
    if (wid == 0) {
        float t = (lane < 8) ? redB[lane] : 0.f;
        t = warp_sum(t);
        if (lane == 0) redB[0] = t;
    }
    __syncthreads();
    const float inv = 1.f / (redB[0] * (float)NHEAD);

    float* wrow = g_Wa + (size_t)i * NTOK;
    for (int j = tid; j < NTOK; j += 256) {
        float p = expf(z[j] - m) * inv;
        wrow[j] = first ? p : (wrow[j] + p);
    }
}

// ---------------- stats: Wf = exp(-dd^2/2)*Wa, reduce sum & sumsq ----------------
__global__ void zero_stats_kernel() { g_stats[0] = 0.0; g_stats[1] = 0.0; }

__global__ __launch_bounds__(256) void wf_stats_kernel(const float* __restrict__ dd)
{
    const size_t total = (size_t)NTOK * NTOK;
    float s1 = 0.f, s2 = 0.f;
    for (size_t idx = (size_t)blockIdx.x * blockDim.x + threadIdx.x;
         idx < total; idx += (size_t)gridDim.x * blockDim.x) {
        float d = dd[idx];
        float wf = expf(-0.5f * d * d) * g_Wa[idx];
        g_Wf[idx] = wf;
        s1 += wf;
        s2 += wf * wf;
    }
    __shared__ float r1[8], r2[8];
    const int lane = threadIdx.x & 31, wid = threadIdx.x >> 5;
    s1 = warp_sum(s1);
    s2 = warp_sum(s2);
    if (lane == 0) { r1[wid] = s1; r2[wid] = s2; }
    __syncthreads();
    if (wid == 0) {
        float a = (lane < 8) ? r1[lane] : 0.f;
        float b = (lane < 8) ? r2[lane] : 0.f;
        a = warp_sum(a);
        b = warp_sum(b);
        if (lane == 0) {
            atomicAdd(&g_stats[0], (double)a);
            atomicAdd(&g_stats[1], (double)b);
        }
    }
}

// ---------------- guided attention: softmax(scores * Ww) in place on g_S ----------------
__global__ __launch_bounds__(256) void masked_softmax_kernel()
{
    __shared__ float z[NTOK];
    __shared__ float redA[8];
    __shared__ float redB[8];
    __shared__ float sh_thr;
    const int i = blockIdx.x, tid = threadIdx.x;
    const int lane = tid & 31, wid = tid >> 5;

    if (tid == 0) {
        double cnt = (double)NTOK * (double)NTOK;
        double mean = g_stats[0] / cnt;
        double var = (g_stats[1] - g_stats[0] * g_stats[0] / cnt) / (cnt - 1.0);
        if (var < 0.0) var = 0.0;
        sh_thr = (float)(mean + 0.5 * sqrt(var));
    }
    __syncthreads();
    const float thr = sh_thr;
    const float invthr = 1.f / thr;

    float* srow = g_S + (size_t)i * NTOK;
    const float* frow = g_Wf + (size_t)i * NTOK;

    float lmax = -1e30f;
    for (int j = tid; j < NTOK; j += 256) {
        float wf = frow[j];
        float ww = (wf < thr) ? wf * invthr : 1.f;
        float v = srow[j] * ww;
        z[j] = v;
        lmax = fmaxf(lmax, v);
    }
    lmax = warp_max(lmax);
    if (lane == 0) redA[wid] = lmax;
    __syncthreads();
    if (wid == 0) {
        float t = (lane < 8) ? redA[lane] : -1e30f;
        t = warp_max(t);
        if (lane == 0) redA[0] = t;
    }
    __syncthreads();
    const float m = redA[0];

    float lsum = 0.f;
    for (int j = tid; j < NTOK; j += 256) lsum += expf(z[j] - m);
    lsum = warp_sum(lsum);
    if (lane == 0) redB[wid] = lsum;
    __syncthreads();
    if (wid == 0) {
        float t = (lane < 8) ? redB[lane] : 0.f;
        t = warp_sum(t);
        if (lane == 0) redB[0] = t;
    }
    __syncthreads();
    const float invs = 1.f / redB[0];

    for (int j = tid; j < NTOK; j += 256)
        srow[j] = expf(z[j] - m) * invs;
}

// ---------------- residual + LayerNorm ----------------
__global__ __launch_bounds__(256) void ln_kernel(
    const float* __restrict__ hs,
    const float* __restrict__ gamma,
    const float* __restrict__ beta,
    float* __restrict__ out)
{
    const int i = blockIdx.x, tid = threadIdx.x;
    const int lane = tid & 31, wid = tid >> 5;
    __shared__ float r1[8], r2[8];

    const float* orow = g_O + (size_t)i * DIM;
    const float* srow = hs + (size_t)i * DIM;

    float x[3];
    float s = 0.f, ss = 0.f;
    #pragma unroll
    for (int t = 0; t < 3; t++) {
        int c = tid + t * 256;
        x[t] = srow[c] + orow[c];
        s += x[t];
        ss += x[t] * x[t];
    }
    s = warp_sum(s);
    ss = warp_sum(ss);
    if (lane == 0) { r1[wid] = s; r2[wid] = ss; }
    __syncthreads();
    if (wid == 0) {
        float a = (lane < 8) ? r1[lane] : 0.f;
        float b = (lane < 8) ? r2[lane] : 0.f;
        a = warp_sum(a);
        b = warp_sum(b);
        if (lane == 0) { r1[0] = a; r2[0] = b; }
    }
    __syncthreads();
    const float mu = r1[0] * (1.f / DIM);
    const float var = r2[0] * (1.f / DIM) - mu * mu;
    const float inv = rsqrtf(var + 1e-5f);

    #pragma unroll
    for (int t = 0; t < 3; t++) {
        int c = tid + t * 256;
        out[(size_t)i * DIM + c] = (x[t] - mu) * inv * gamma[c] + beta[c];
    }
}

// ---------------- host ----------------
extern "C" void kernel_launch(void* const* d_in, const int* in_sizes, int n_in,
                              void* d_out, int out_size)
{
    const float* h_a  = (const float*)d_in[0];
    const float* h_s  = (const float*)d_in[1];
    const float* dep  = (const float*)d_in[2];
    const float* Wq_a = (const float*)d_in[3];
    const float* bq_a = (const float*)d_in[4];
    const float* Wk_a = (const float*)d_in[5];
    const float* bk_a = (const float*)d_in[6];
    const float* Wq   = (const float*)d_in[7];
    const float* bq   = (const float*)d_in[8];
    const float* Wk   = (const float*)d_in[9];
    const float* bk   = (const float*)d_in[10];
    const float* Wv   = (const float*)d_in[11];
    const float* bv   = (const float*)d_in[12];
    const float* lng  = (const float*)d_in[13];
    const float* lnb  = (const float*)d_in[14];
    float* out = (float*)d_out;

    float *qa, *ka, *Q, *K, *V, *O, *S;
    cudaGetSymbolAddress((void**)&qa, g_qa);
    cudaGetSymbolAddress((void**)&ka, g_ka);
    cudaGetSymbolAddress((void**)&Q,  g_Q);
    cudaGetSymbolAddress((void**)&K,  g_K);
    cudaGetSymbolAddress((void**)&V,  g_V);
    cudaGetSymbolAddress((void**)&O,  g_O);
    cudaGetSymbolAddress((void**)&S,  g_S);

    const dim3 blk(256);
    const dim3 gProj(DIM / 128, NTOK / 128);    // 6 x 24
    const dim3 gNN(NTOK / 128, NTOK / 128);     // 24 x 24

    // projections: X @ W^T + b
    gemm_nt<<<gProj, blk>>>(h_a, DIM, Wq_a, DIM, qa, DIM, DIM, bq_a, 1.f);
    gemm_nt<<<gProj, blk>>>(h_a, DIM, Wk_a, DIM, ka, DIM, DIM, bk_a, 1.f);
    gemm_nt<<<gProj, blk>>>(h_s, DIM, Wq,   DIM, Q,  DIM, DIM, bq,   1.f);
    gemm_nt<<<gProj, blk>>>(h_s, DIM, Wk,   DIM, K,  DIM, DIM, bk,   1.f);
    gemm_nt<<<gProj, blk>>>(h_s, DIM, Wv,   DIM, V,  DIM, DIM, bv,   1.f);

    // per-head logits + softmax, averaged into g_Wa
    const float head_scale = 0.125f;  // 1/sqrt(64)
    for (int h = 0; h < NHEAD; h++) {
        gemm_nt<<<gNN, blk>>>(qa + h * HDIM, DIM, ka + h * HDIM, DIM,
                              S, NTOK, HDIM, nullptr, head_scale);
        softmax_acc_kernel<<<NTOK, 256>>>(h == 0 ? 1 : 0);
    }

    // fused weights + threshold stats
    zero_stats_kernel<<<1, 1>>>();
    wf_stats_kernel<<<2048, 256>>>(dep);

    // guided attention: scores, masked softmax, attn @ V
    const float score_scale = 1.f / sqrtf((float)DIM);
    gemm_nt<<<gNN, blk>>>(Q, DIM, K, DIM, S, NTOK, DIM, nullptr, score_scale);
    masked_softmax_kernel<<<NTOK, 256>>>();
    gemm_nn<<<gProj, blk>>>(S, NTOK, V, DIM, O, DIM, NTOK, nullptr, 1.f);

    // residual + LayerNorm
    ln_kernel<<<NTOK, 256>>>(h_s, lng, lnb, out);
}

// round 2
// speedup vs baseline: 1.8292x; 1.8292x over previous
#include <cuda_runtime.h>
#include <math.h>
#include <stdint.h>

#define NTOK 3072
#define DIM  768
#define NHEAD 12
#define HDIM 64

// ---------------- static device scratch ----------------
__device__ float g_qa[NTOK * DIM];
__device__ float g_ka[NTOK * DIM];
__device__ float g_Q [NTOK * DIM];
__device__ float g_K [NTOK * DIM];
__device__ float g_V [NTOK * DIM];
__device__ float g_O [NTOK * DIM];
__device__ float g_S [(size_t)NTOK * NTOK];            // scores / attn
__device__ float g_Sh[(size_t)NHEAD * NTOK * NTOK];    // per-head logits
__device__ float g_Wf[(size_t)NTOK * NTOK];            // fused weights
__device__ double g_stats[2];

// ---------------- helpers ----------------
__device__ __forceinline__ float warp_max(float v) {
    #pragma unroll
    for (int o = 16; o; o >>= 1) v = fmaxf(v, __shfl_xor_sync(0xffffffffu, v, o));
    return v;
}
__device__ __forceinline__ float warp_sum(float v) {
    #pragma unroll
    for (int o = 16; o; o >>= 1) v += __shfl_xor_sync(0xffffffffu, v, o);
    return v;
}
__device__ __forceinline__ uint32_t f2tf(float x) {
    uint32_t y;
    asm("cvt.rna.tf32.f32 %0, %1;" : "=r"(y) : "f"(x));
    return y;
}
__device__ __forceinline__ void mma_tf32(float* d, const uint32_t* a, const uint32_t* b) {
    asm volatile(
        "mma.sync.aligned.m16n8k8.row.col.f32.tf32.tf32.f32 "
        "{%0,%1,%2,%3}, {%4,%5,%6,%7}, {%8,%9}, {%0,%1,%2,%3};\n"
        : "+f"(d[0]), "+f"(d[1]), "+f"(d[2]), "+f"(d[3])
        : "r"(a[0]), "r"(a[1]), "r"(a[2]), "r"(a[3]), "r"(b[0]), "r"(b[1]));
}

#define SMS 136  // smem row stride (128 + 8): conflict-free fragment loads

// ---------------- tf32 tensor-core NT GEMM: C = scale*A.B^T (+bias), batched ----------------
// A row-major M x K (lda), B row-major N x K (ldb). Tiles 128x128x16, 8 warps (4x2).
__global__ __launch_bounds__(256, 2) void gemm_nt_tc(
    const float* __restrict__ A, int lda, long long strideA,
    const float* __restrict__ B, int ldb, long long strideB,
    float* __restrict__ C, int ldc, long long strideC,
    int K, const float* __restrict__ bias, float scale)
{
    __shared__ uint32_t As[16][SMS];
    __shared__ uint32_t Bs[16][SMS];

    const int z = blockIdx.z;
    A += (size_t)z * strideA;
    B += (size_t)z * strideB;
    C += (size_t)z * strideC;

    const int tid = threadIdx.x;
    const int row0 = blockIdx.y * 128, col0 = blockIdx.x * 128;
    const int wid = tid >> 5, lane = tid & 31;
    const int wm = wid & 3, wn = wid >> 2;   // 4 x 2 warp grid
    const int g = lane >> 2, tig = lane & 3;

    float acc[2][8][4];
    #pragma unroll
    for (int i = 0; i < 2; i++)
        #pragma unroll
        for (int j = 0; j < 8; j++)
            #pragma unroll
            for (int q = 0; q < 4; q++) acc[i][j][q] = 0.f;

    const int lrow = tid >> 2;   // 0..63
    const int lkv  = tid & 3;    // float4 slot in k

    for (int k0 = 0; k0 < K; k0 += 16) {
        #pragma unroll
        for (int h = 0; h < 2; h++) {
            int r = lrow + h * 64;
            float4 v = *(const float4*)(A + (size_t)(row0 + r) * lda + k0 + lkv * 4);
            As[lkv * 4 + 0][r] = f2tf(v.x);
            As[lkv * 4 + 1][r] = f2tf(v.y);
            As[lkv * 4 + 2][r] = f2tf(v.z);
            As[lkv * 4 + 3][r] = f2tf(v.w);
        }
        #pragma unroll
        for (int h = 0; h < 2; h++) {
            int r = lrow + h * 64;
            float4 v = *(const float4*)(B + (size_t)(col0 + r) * ldb + k0 + lkv * 4);
            Bs[lkv * 4 + 0][r] = f2tf(v.x);
            Bs[lkv * 4 + 1][r] = f2tf(v.y);
            Bs[lkv * 4 + 2][r] = f2tf(v.z);
            Bs[lkv * 4 + 3][r] = f2tf(v.w);
        }
        __syncthreads();
        #pragma unroll
        for (int kk = 0; kk < 16; kk += 8) {
            uint32_t af[2][4];
            #pragma unroll
            for (int mi = 0; mi < 2; mi++) {
                int rb = wm * 32 + mi * 16;
                af[mi][0] = As[kk + tig    ][rb + g];
                af[mi][1] = As[kk + tig    ][rb + g + 8];
                af[mi][2] = As[kk + tig + 4][rb + g];
                af[mi][3] = As[kk + tig + 4][rb + g + 8];
            }
            #pragma unroll
            for (int ni = 0; ni < 8; ni++) {
                int cb = wn * 64 + ni * 8;
                uint32_t bf[2];
                bf[0] = Bs[kk + tig    ][cb + g];
                bf[1] = Bs[kk + tig + 4][cb + g];
                #pragma unroll
                for (int mi = 0; mi < 2; mi++) mma_tf32(acc[mi][ni], af[mi], bf);
            }
        }
        __syncthreads();
    }

    #pragma unroll
    for (int mi = 0; mi < 2; mi++) {
        #pragma unroll
        for (int gg = 0; gg < 2; gg++) {
            int r = row0 + wm * 32 + mi * 16 + g + gg * 8;
            #pragma unroll
            for (int ni = 0; ni < 8; ni++) {
                int c = col0 + wn * 64 + ni * 8 + tig * 2;
                float2 v;
                v.x = acc[mi][ni][gg * 2 + 0] * scale;
                v.y = acc[mi][ni][gg * 2 + 1] * scale;
                if (bias) { v.x += bias[c]; v.y += bias[c + 1]; }
                *(float2*)(C + (size_t)r * ldc + c) = v;
            }
        }
    }
}

// ---------------- tf32 tensor-core NN GEMM: C = A @ B ----------------
__global__ __launch_bounds__(256, 2) void gemm_nn_tc(
    const float* __restrict__ A, int lda,
    const float* __restrict__ B, int ldb,
    float* __restrict__ C, int ldc, int K)
{
    __shared__ uint32_t As[16][SMS];
    __shared__ uint32_t Bs[16][SMS];

    const int tid = threadIdx.x;
    const int row0 = blockIdx.y * 128, col0 = blockIdx.x * 128;
    const int wid = tid >> 5, lane = tid & 31;
    const int wm = wid & 3, wn = wid >> 2;
    const int g = lane >> 2, tig = lane & 3;

    float acc[2][8][4];
    #pragma unroll
    for (int i = 0; i < 2; i++)
        #pragma unroll
        for (int j = 0; j < 8; j++)
            #pragma unroll
            for (int q = 0; q < 4; q++) acc[i][j][q] = 0.f;

    const int lrow = tid >> 2;
    const int lkv  = tid & 3;
    const int bkk  = tid >> 5;       // 0..7
    const int bn4  = tid & 31;       // float4 slot in n

    for (int k0 = 0; k0 < K; k0 += 16) {
        #pragma unroll
        for (int h = 0; h < 2; h++) {
            int r = lrow + h * 64;
            float4 v = *(const float4*)(A + (size_t)(row0 + r) * lda + k0 + lkv * 4);
            As[lkv * 4 + 0][r] = f2tf(v.x);
            As[lkv * 4 + 1][r] = f2tf(v.y);
            As[lkv * 4 + 2][r] = f2tf(v.z);
            As[lkv * 4 + 3][r] = f2tf(v.w);
        }
        #pragma unroll
        for (int h = 0; h < 2; h++) {
            int kk = bkk + h * 8;
            float4 v = *(const float4*)(B + (size_t)(k0 + kk) * ldb + col0 + bn4 * 4);
            uint4 u;
            u.x = f2tf(v.x); u.y = f2tf(v.y); u.z = f2tf(v.z); u.w = f2tf(v.w);
            *(uint4*)(&Bs[kk][bn4 * 4]) = u;
        }
        __syncthreads();
        #pragma unroll
        for (int kk = 0; kk < 16; kk += 8) {
            uint32_t af[2][4];
            #pragma unroll
            for (int mi = 0; mi < 2; mi++) {
                int rb = wm * 32 + mi * 16;
                af[mi][0] = As[kk + tig    ][rb + g];
                af[mi][1] = As[kk + tig    ][rb + g + 8];
                af[mi][2] = As[kk + tig + 4][rb + g];
                af[mi][3] = As[kk + tig + 4][rb + g + 8];
            }
            #pragma unroll
            for (int ni = 0; ni < 8; ni++) {
                int cb = wn * 64 + ni * 8;
                uint32_t bf[2];
                bf[0] = Bs[kk + tig    ][cb + g];
                bf[1] = Bs[kk + tig + 4][cb + g];
                #pragma unroll
                for (int mi = 0; mi < 2; mi++) mma_tf32(acc[mi][ni], af[mi], bf);
            }
        }
        __syncthreads();
    }

    #pragma unroll
    for (int mi = 0; mi < 2; mi++) {
        #pragma unroll
        for (int gg = 0; gg < 2; gg++) {
            int r = row0 + wm * 32 + mi * 16 + g + gg * 8;
            #pragma unroll
            for (int ni = 0; ni < 8; ni++) {
                int c = col0 + wn * 64 + ni * 8 + tig * 2;
                float2 v;
                v.x = acc[mi][ni][gg * 2 + 0];
                v.y = acc[mi][ni][gg * 2 + 1];
                *(float2*)(C + (size_t)r * ldc + c) = v;
            }
        }
    }
}

// ---------------- fused: 12-head softmax avg + Gaussian weight + stats ----------------
__global__ void zero_stats_kernel() { g_stats[0] = 0.0; g_stats[1] = 0.0; }

extern __shared__ float sh_rows[];  // NHEAD * NTOK floats

__global__ __launch_bounds__(256) void headsmax_wf_kernel(const float* __restrict__ dd)
{
    __shared__ float redA[8], redB[8];
    __shared__ float mh[NHEAD], invZ[NHEAD];
    const int i = blockIdx.x, tid = threadIdx.x;
    const int lane = tid & 31, wid = tid >> 5;

    // load 12 head rows, per-head max
    #pragma unroll
    for (int h = 0; h < NHEAD; h++) {
        const float* row = g_Sh + (size_t)h * NTOK * NTOK + (size_t)i * NTOK;
        float lmax = -1e30f;
        for (int j = tid; j < NTOK; j += 256) {
            float v = row[j];
            sh_rows[h * NTOK + j] = v;
            lmax = fmaxf(lmax, v);
        }
        lmax = warp_max(lmax);
        if (lane == 0) redA[wid] = lmax;
        __syncthreads();
        if (wid == 0) {
            float t = (lane < 8) ? redA[lane] : -1e30f;
            t = warp_max(t);
            if (lane == 0) mh[h] = t;
        }
        __syncthreads();
    }

    // exp in place + per-head sums
    #pragma unroll
    for (int h = 0; h < NHEAD; h++) {
        const float m = mh[h];
        float lsum = 0.f;
        for (int j = tid; j < NTOK; j += 256) {
            float e = __expf(sh_rows[h * NTOK + j] - m);
            sh_rows[h * NTOK + j] = e;
            lsum += e;
        }
        lsum = warp_sum(lsum);
        if (lane == 0) redB[wid] = lsum;
        __syncthreads();
        if (wid == 0) {
            float t = (lane < 8) ? redB[lane] : 0.f;
            t = warp_sum(t);
            if (lane == 0) invZ[h] = 1.f / (t * (float)NHEAD);
        }
        __syncthreads();
    }

    // combine heads, multiply by structural weight, write Wf, accumulate stats
    float iz[NHEAD];
    #pragma unroll
    for (int h = 0; h < NHEAD; h++) iz[h] = invZ[h];

    const float* drow = dd + (size_t)i * NTOK;
    float* frow = g_Wf + (size_t)i * NTOK;
    float s1 = 0.f, s2 = 0.f;
    for (int j = tid; j < NTOK; j += 256) {
        float wa = 0.f;
        #pragma unroll
        for (int h = 0; h < NHEAD; h++) wa += sh_rows[h * NTOK + j] * iz[h];
        float d = drow[j];
        float wf = __expf(-0.5f * d * d) * wa;
        frow[j] = wf;
        s1 += wf;
        s2 += wf * wf;
    }
    s1 = warp_sum(s1);
    s2 = warp_sum(s2);
    if (lane == 0) { redA[wid] = s1; redB[wid] = s2; }
    __syncthreads();
    if (wid == 0) {
        float a = (lane < 8) ? redA[lane] : 0.f;
        float b = (lane < 8) ? redB[lane] : 0.f;
        a = warp_sum(a);
        b = warp_sum(b);
        if (lane == 0) {
            atomicAdd(&g_stats[0], (double)a);
            atomicAdd(&g_stats[1], (double)b);
        }
    }
}

// ---------------- guided attention masked softmax (in place on g_S) ----------------
__global__ __launch_bounds__(256) void masked_softmax_kernel()
{
    __shared__ float z[NTOK];
    __shared__ float redA[8], redB[8];
    __shared__ float sh_thr;
    const int i = blockIdx.x, tid = threadIdx.x;
    const int lane = tid & 31, wid = tid >> 5;

    if (tid == 0) {
        double cnt = (double)NTOK * (double)NTOK;
        double mean = g_stats[0] / cnt;
        double var = (g_stats[1] - g_stats[0] * g_stats[0] / cnt) / (cnt - 1.0);
        if (var < 0.0) var = 0.0;
        sh_thr = (float)(mean + 0.5 * sqrt(var));
    }
    __syncthreads();
    const float thr = sh_thr;
    const float invthr = 1.f / thr;

    float* srow = g_S + (size_t)i * NTOK;
    const float* frow = g_Wf + (size_t)i * NTOK;

    float lmax = -1e30f;
    for (int j = tid; j < NTOK; j += 256) {
        float wf = frow[j];
        float ww = (wf < thr) ? wf * invthr : 1.f;
        float v = srow[j] * ww;
        z[j] = v;
        lmax = fmaxf(lmax, v);
    }
    lmax = warp_max(lmax);
    if (lane == 0) redA[wid] = lmax;
    __syncthreads();
    if (wid == 0) {
        float t = (lane < 8) ? redA[lane] : -1e30f;
        t = warp_max(t);
        if (lane == 0) redA[0] = t;
    }
    __syncthreads();
    const float m = redA[0];

    float lsum = 0.f;
    for (int j = tid; j < NTOK; j += 256) {
        float e = __expf(z[j] - m);
        z[j] = e;
        lsum += e;
    }
    lsum = warp_sum(lsum);
    if (lane == 0) redB[wid] = lsum;
    __syncthreads();
    if (wid == 0) {
        float t = (lane < 8) ? redB[lane] : 0.f;
        t = warp_sum(t);
        if (lane == 0) redB[0] = t;
    }
    __syncthreads();
    const float invs = 1.f / redB[0];

    for (int j = tid; j < NTOK; j += 256)
        srow[j] = z[j] * invs;
}

// ---------------- residual + LayerNorm ----------------
__global__ __launch_bounds__(256) void ln_kernel(
    const float* __restrict__ hs,
    const float* __restrict__ gamma,
    const float* __restrict__ beta,
    float* __restrict__ out)
{
    const int i = blockIdx.x, tid = threadIdx.x;
    const int lane = tid & 31, wid = tid >> 5;
    __shared__ float r1[8], r2[8];

    const float* orow = g_O + (size_t)i * DIM;
    const float* srow = hs + (size_t)i * DIM;

    float x[3];
    float s = 0.f, ss = 0.f;
    #pragma unroll
    for (int t = 0; t < 3; t++) {
        int c = tid + t * 256;
        x[t] = srow[c] + orow[c];
        s += x[t];
        ss += x[t] * x[t];
    }
    s = warp_sum(s);
    ss = warp_sum(ss);
    if (lane == 0) { r1[wid] = s; r2[wid] = ss; }
    __syncthreads();
    if (wid == 0) {
        float a = (lane < 8) ? r1[lane] : 0.f;
        float b = (lane < 8) ? r2[lane] : 0.f;
        a = warp_sum(a);
        b = warp_sum(b);
        if (lane == 0) { r1[0] = a; r2[0] = b; }
    }
    __syncthreads();
    const float mu = r1[0] * (1.f / DIM);
    const float var = r2[0] * (1.f / DIM) - mu * mu;
    const float inv = rsqrtf(var + 1e-5f);

    #pragma unroll
    for (int t = 0; t < 3; t++) {
        int c = tid + t * 256;
        out[(size_t)i * DIM + c] = (x[t] - mu) * inv * gamma[c] + beta[c];
    }
}

// ---------------- host ----------------
extern "C" void kernel_launch(void* const* d_in, const int* in_sizes, int n_in,
                              void* d_out, int out_size)
{
    const float* h_a  = (const float*)d_in[0];
    const float* h_s  = (const float*)d_in[1];
    const float* dep  = (const float*)d_in[2];
    const float* Wq_a = (const float*)d_in[3];
    const float* bq_a = (const float*)d_in[4];
    const float* Wk_a = (const float*)d_in[5];
    const float* bk_a = (const float*)d_in[6];
    const float* Wq   = (const float*)d_in[7];
    const float* bq   = (const float*)d_in[8];
    const float* Wk   = (const float*)d_in[9];
    const float* bk   = (const float*)d_in[10];
    const float* Wv   = (const float*)d_in[11];
    const float* bv   = (const float*)d_in[12];
    const float* lng  = (const float*)d_in[13];
    const float* lnb  = (const float*)d_in[14];
    float* out = (float*)d_out;

    float *qa, *ka, *Q, *K, *V, *O, *S, *Sh;
    cudaGetSymbolAddress((void**)&qa, g_qa);
    cudaGetSymbolAddress((void**)&ka, g_ka);
    cudaGetSymbolAddress((void**)&Q,  g_Q);
    cudaGetSymbolAddress((void**)&K,  g_K);
    cudaGetSymbolAddress((void**)&V,  g_V);
    cudaGetSymbolAddress((void**)&O,  g_O);
    cudaGetSymbolAddress((void**)&S,  g_S);
    cudaGetSymbolAddress((void**)&Sh, g_Sh);

    static int smem_set = 0;
    if (!smem_set) {
        cudaFuncSetAttribute(headsmax_wf_kernel,
                             cudaFuncAttributeMaxDynamicSharedMemorySize,
                             NHEAD * NTOK * sizeof(float));
        smem_set = 1;
    }

    const dim3 blk(256);
    const dim3 gProj(DIM / 128, NTOK / 128);          // 6 x 24
    const dim3 gNN(NTOK / 128, NTOK / 128);           // 24 x 24
    const dim3 gHeads(NTOK / 128, NTOK / 128, NHEAD); // 24 x 24 x 12

    // projections: X @ W^T + b (tensor cores, tf32)
    gemm_nt_tc<<<gProj, blk>>>(h_a, DIM, 0, Wq_a, DIM, 0, qa, DIM, 0, DIM, bq_a, 1.f);
    gemm_nt_tc<<<gProj, blk>>>(h_a, DIM, 0, Wk_a, DIM, 0, ka, DIM, 0, DIM, bk_a, 1.f);
    gemm_nt_tc<<<gProj, blk>>>(h_s, DIM, 0, Wq,   DIM, 0, Q,  DIM, 0, DIM, bq,   1.f);
    gemm_nt_tc<<<gProj, blk>>>(h_s, DIM, 0, Wk,   DIM, 0, K,  DIM, 0, DIM, bk,   1.f);
    gemm_nt_tc<<<gProj, blk>>>(h_s, DIM, 0, Wv,   DIM, 0, V,  DIM, 0, DIM, bv,   1.f);

    // all 12 per-head logit GEMMs in one batched launch
    gemm_nt_tc<<<gHeads, blk>>>(qa, DIM, HDIM, ka, DIM, HDIM,
                                Sh, NTOK, (long long)NTOK * NTOK,
                                HDIM, nullptr, 0.125f);

    // fused 12-head softmax + average + structural weight + stats
    zero_stats_kernel<<<1, 1>>>();
    headsmax_wf_kernel<<<NTOK, 256, NHEAD * NTOK * sizeof(float)>>>(dep);

    // guided attention
    const float score_scale = 1.f / sqrtf((float)DIM);
    gemm_nt_tc<<<gNN, blk>>>(Q, DIM, 0, K, DIM, 0, S, NTOK, 0, DIM, nullptr, score_scale);
    masked_softmax_kernel<<<NTOK, 256>>>();
    gemm_nn_tc<<<gProj, blk>>>(S, NTOK, V, DIM, O, DIM, NTOK);

    // residual + LayerNorm
    ln_kernel<<<NTOK, 256>>>(h_s, lng, lnb, out);
}